// round 1
// baseline (speedup 1.0000x reference)
#include <cuda_runtime.h>
#include <math.h>

#define BATCH 300
#define ICH   256
#define HIN   38
#define WIN   38
#define OC1   128
#define H1    39
#define W1D   39
#define NPOS1 (H1*W1D)   /* 1521 */
#define KPOS  (38*38)    /* 1444 */

// scratch: conv1 output (relu'd), plus per-batch argmax results
__device__ float g_x[BATCH * OC1 * NPOS1];
__device__ int   g_bf[BATCH];
__device__ float g_bv[BATCH];

// ---------------------------------------------------------------------------
// K1: conv1 = relu(conv2d(base_feat, W1, pad=1)) -> g_x  (300,128,39,39)
// grid (39 rows, 300 batches), 256 threads.
// Each block: 1 output row (39 px, padded to 40), all 128 OC.
// Thread: 4 OC x 5 px accumulators.
// ---------------------------------------------------------------------------
__global__ __launch_bounds__(256) void conv1_kernel(
    const float* __restrict__ in, const float* __restrict__ w,
    const float* __restrict__ bias)
{
    __shared__ __align__(16) float sA[16 * 516];   // [icL] -> tap*128 + oc (row stride 516)
    __shared__ float sB[16 * 84];                  // [icL][r2*42 + col], col = input col + 1

    const int oh = blockIdx.x;
    const int b  = blockIdx.y;
    const int t  = threadIdx.x;
    const int oc0 = (t >> 3) * 4;   // 32 groups of 4 OC
    const int px0 = (t & 7) * 5;    // 8 groups of 5 px

    float acc0[5] = {0,0,0,0,0};
    float acc1[5] = {0,0,0,0,0};
    float acc2[5] = {0,0,0,0,0};
    float acc3[5] = {0,0,0,0,0};

    const float4* w4 = (const float4*)w;   // one float4 = one (oc,ic): taps 0..3

    for (int chunk = 0; chunk < 16; ++chunk) {
        const int ic0 = chunk * 16;
        __syncthreads();   // protect smem reuse from previous chunk's compute
        // ---- load weights: 16 ic x 4 tap x 128 oc ----
        #pragma unroll
        for (int i = 0; i < 8; ++i) {
            int e = t + i * 256;               // 0..2047 float4s
            int oc = e >> 4, icL = e & 15;
            float4 wv = w4[oc * 256 + ic0 + icL];
            int base = icL * 516 + oc;
            sA[base        ] = wv.x;
            sA[base + 128  ] = wv.y;
            sA[base + 256  ] = wv.z;
            sA[base + 384  ] = wv.w;
        }
        // ---- zero the pad columns (0, 39, 40, 41) ----
        if (t < 128) {
            int icL = t >> 3, r2 = (t >> 2) & 1, ci = t & 3;
            int col = (ci == 0) ? 0 : 38 + ci;
            sB[icL * 84 + r2 * 42 + col] = 0.f;
        }
        // ---- load input rows oh-1, oh (16 ic x 2 rows x 38 cols) ----
        #pragma unroll
        for (int i = 0; i < 5; ++i) {
            int e = t + i * 256;
            if (e < 1216) {
                int icL = e / 76, rr = e % 76;
                int r2 = rr / 38, c = rr % 38;
                int r = oh - 1 + r2;
                float v = (r >= 0 && r < HIN)
                        ? in[((b * ICH + ic0 + icL) * HIN + r) * WIN + c] : 0.f;
                sB[icL * 84 + r2 * 42 + c + 1] = v;
            }
        }
        __syncthreads();
        // ---- compute ----
        #pragma unroll
        for (int icL = 0; icL < 16; ++icL) {
            #pragma unroll
            for (int kh = 0; kh < 2; ++kh) {
                #pragma unroll
                for (int kw = 0; kw < 2; ++kw) {
                    float4 a = *(const float4*)&sA[icL * 516 + (kh * 2 + kw) * 128 + oc0];
                    const float* bp = &sB[icL * 84 + kh * 42 + px0 + kw];
                    #pragma unroll
                    for (int p = 0; p < 5; ++p) {
                        float bv = bp[p];
                        acc0[p] += a.x * bv;
                        acc1[p] += a.y * bv;
                        acc2[p] += a.z * bv;
                        acc3[p] += a.w * bv;
                    }
                }
            }
        }
    }
    float4 bi = *(const float4*)&bias[oc0];
    #pragma unroll
    for (int p = 0; p < 5; ++p) {
        int ow = px0 + p;
        if (ow < W1D) {
            int base = ((b * OC1 + oc0) * H1 + oh) * W1D + ow;
            float v;
            v = acc0[p] + bi.x; g_x[base            ] = v > 0.f ? v : 0.f;
            v = acc1[p] + bi.y; g_x[base + NPOS1    ] = v > 0.f ? v : 0.f;
            v = acc2[p] + bi.z; g_x[base + 2*NPOS1  ] = v > 0.f ? v : 0.f;
            v = acc3[p] + bi.w; g_x[base + 3*NPOS1  ] = v > 0.f ? v : 0.f;
        }
    }
}

// ---------------------------------------------------------------------------
// K2: difference conv (Wc[a+4]-Wc[a]) + global argmax over f = a*1444 + pos.
// sigmoid is monotone => argmax of diff == argmax of softmax score.
// 1 block per batch, 256 threads, each owning 6 positions x 4 anchors.
// ---------------------------------------------------------------------------
__global__ __launch_bounds__(256) void cls_argmax_kernel(
    const float* __restrict__ Wc, const float* __restrict__ bc)
{
    __shared__ __align__(16) float wds[128 * 16];   // [ic][tap*4 + a]
    __shared__ float xs[4 * NPOS1];                 // 4 ic chunk
    __shared__ float rv[256];
    __shared__ int   rf[256];

    const int b = blockIdx.x, t = threadIdx.x;

    // weight differences: wds[ic][tap][a] = Wc[a+4] - Wc[a]
    #pragma unroll
    for (int i = 0; i < 8; ++i) {
        int e = t + i * 256;                 // 0..2047
        int ic = e >> 4, tap = (e >> 2) & 3, a = e & 3;
        wds[ic * 16 + tap * 4 + a] =
            Wc[(a + 4) * 512 + ic * 4 + tap] - Wc[a * 512 + ic * 4 + tap];
    }

    int  offs[6];
    bool valid[6];
    #pragma unroll
    for (int i = 0; i < 6; ++i) {
        int p = t + i * 256;
        valid[i] = (p < KPOS);
        int pc = valid[i] ? p : 0;
        offs[i] = (pc / 38) * 39 + (pc % 38);   // pos -> x row offset
    }

    float acc[6][4];
    #pragma unroll
    for (int i = 0; i < 6; ++i)
        #pragma unroll
        for (int a = 0; a < 4; ++a) acc[i][a] = 0.f;

    const float* xb = g_x + (size_t)b * OC1 * NPOS1;

    for (int chunk = 0; chunk < 32; ++chunk) {
        __syncthreads();
        #pragma unroll
        for (int i = 0; i < 24; ++i) {
            int e = t + i * 256;
            if (e < 4 * NPOS1) xs[e] = xb[chunk * 4 * NPOS1 + e];
        }
        __syncthreads();
        #pragma unroll
        for (int icL = 0; icL < 4; ++icL) {
            int icg = chunk * 4 + icL;
            #pragma unroll
            for (int tap = 0; tap < 4; ++tap) {
                float4 wv = *(const float4*)&wds[icg * 16 + tap * 4];
                int bidx = icL * NPOS1 + (tap >> 1) * 39 + (tap & 1);
                #pragma unroll
                for (int i = 0; i < 6; ++i) {
                    float xv = xs[bidx + offs[i]];
                    acc[i][0] += wv.x * xv;
                    acc[i][1] += wv.y * xv;
                    acc[i][2] += wv.z * xv;
                    acc[i][3] += wv.w * xv;
                }
            }
        }
    }

    float bd[4];
    #pragma unroll
    for (int a = 0; a < 4; ++a) bd[a] = bc[a + 4] - bc[a];

    float bv = -1e30f; int bf = 0x7fffffff;
    #pragma unroll
    for (int i = 0; i < 6; ++i) {
        if (valid[i]) {
            int p = t + i * 256;
            #pragma unroll
            for (int a = 0; a < 4; ++a) {
                float v = acc[i][a] + bd[a];
                int f = a * KPOS + p;
                if (v > bv || (v == bv && f < bf)) { bv = v; bf = f; }
            }
        }
    }
    rv[t] = bv; rf[t] = bf;
    __syncthreads();
    for (int s = 128; s > 0; s >>= 1) {
        if (t < s) {
            float v2 = rv[t + s]; int f2 = rf[t + s];
            if (v2 > rv[t] || (v2 == rv[t] && f2 < rf[t])) { rv[t] = v2; rf[t] = f2; }
        }
        __syncthreads();
    }
    if (t == 0) { g_bf[b] = rf[0]; g_bv[b] = rv[0]; }
}

// ---------------------------------------------------------------------------
// K3: deltas conv at the single selected position (4 channels), box assembly.
// f interpreted in proposal space: pos = f>>2, anchor = f&3.
// 1 block per batch, 128 threads (one per ic).
// ---------------------------------------------------------------------------
__global__ __launch_bounds__(128) void box_kernel(
    const float* __restrict__ Wb, const float* __restrict__ bb,
    const float* __restrict__ anchors, const float* __restrict__ im_info,
    float* __restrict__ out)
{
    __shared__ float red[4][128];
    const int b = blockIdx.x, ic = threadIdx.x;
    const int f  = g_bf[b];
    const int kp = f >> 2, ap = f & 3;
    const int hp = kp / 38, wp = kp % 38;

    const float* xb = g_x + ((size_t)b * OC1 + ic) * NPOS1 + hp * 39 + wp;
    float x0 = xb[0], x1 = xb[1], x2 = xb[39], x3 = xb[40];

    #pragma unroll
    for (int j = 0; j < 4; ++j) {
        const float* wq = Wb + (ap * 4 + j) * 512 + ic * 4;
        red[j][ic] = x0 * wq[0] + x1 * wq[1] + x2 * wq[2] + x3 * wq[3];
    }
    __syncthreads();
    if (ic < 4) {
        float s = 0.f;
        #pragma unroll 8
        for (int k = 0; k < 128; ++k) s += red[ic][k];
        s += bb[ap * 4 + ic];
        float shift = (ic & 1) ? hp * 16.f : wp * 16.f;
        float sc = im_info[0];
        float box = (anchors[ap * 4 + ic] + shift + s) * sc;
        out[b * 9 + ic]     = truncf(box / sc);
        out[b * 9 + 4 + ic] = box;
    }
    if (ic == 4) out[b * 9 + 8] = 1.f / (1.f + expf(-g_bv[b]));
}

// ---------------------------------------------------------------------------
// K4: proposal loss (single thread). Replicates reference exactly, including
// the "maximum" used for xi2/yi2.
// ---------------------------------------------------------------------------
__global__ void loss_kernel(const float* __restrict__ gt,
                            const int* __restrict__ central,
                            float* __restrict__ out, int out_size)
{
    int idx = central[0];            // FRAMES_PER_VIDEO * 0 + central_pos
    bool valid = idx < BATCH;
    int ix = idx < 0 ? 0 : (idx > BATCH - 1 ? BATCH - 1 : idx);
    float vb0 = out[ix * 9 + 4], vb1 = out[ix * 9 + 5];
    float vb2 = out[ix * 9 + 6], vb3 = out[ix * 9 + 7];
    float vs  = out[ix * 9 + 8];
    float xi1 = fmaxf(gt[0], vb0);
    float yi1 = fmaxf(gt[1], vb1);
    float xi2 = fmaxf(gt[2], vb2);
    float yi2 = fmaxf(gt[3], vb3);
    float inter = (xi2 - xi1) * (yi2 - yi1);
    float a1 = (gt[2] - gt[0]) * (gt[3] - gt[1]);
    float a2 = (vb2 - vb0) * (vb3 - vb1);
    float iou = inter / (a1 + a2 - inter);
    float lv = (iou > 0.7f) ? -logf(vs + 1e-5f) : -logf(1.f - vs + 1e-5f);
    out[out_size - 1] = valid ? lv : 0.f;
}

// ---------------------------------------------------------------------------
extern "C" void kernel_launch(void* const* d_in, const int* in_sizes, int n_in,
                              void* d_out, int out_size)
{
    const float* base_feat = (const float*)d_in[0];
    const int*   central   = (const int*)  d_in[1];
    const float* im_info   = (const float*)d_in[2];
    const float* gt_boxes  = (const float*)d_in[3];
    const float* W1        = (const float*)d_in[4];
    const float* b1        = (const float*)d_in[5];
    const float* Wc        = (const float*)d_in[6];
    const float* bc        = (const float*)d_in[7];
    const float* Wb        = (const float*)d_in[8];
    const float* bb        = (const float*)d_in[9];
    const float* anchors   = (const float*)d_in[10];
    float* out = (float*)d_out;

    conv1_kernel<<<dim3(H1, BATCH), 256>>>(base_feat, W1, b1);
    cls_argmax_kernel<<<BATCH, 256>>>(Wc, bc);
    box_kernel<<<BATCH, 128>>>(Wb, bb, anchors, im_info, out);
    loss_kernel<<<1, 1>>>(gt_boxes, central, out, out_size);
}

// round 2
// speedup vs baseline: 1.0035x; 1.0035x over previous
#include <cuda_runtime.h>
#include <math.h>

#define BATCH 300
#define ICH   256
#define HIN   38
#define WIN   38
#define OC1   128
#define H1    39
#define W1D   39
#define NPOS1 (H1*W1D)   /* 1521 */
#define KPOS  (38*38)    /* 1444 */

// scratch: conv1 output (relu'd), plus per-batch argmax results
__device__ float g_x[BATCH * OC1 * NPOS1];
__device__ int   g_bf[BATCH];
__device__ float g_bv[BATCH];

// ---------------------------------------------------------------------------
// K1: conv1 = relu(conv2d(base_feat, W1, pad=1)) -> g_x  (300,128,39,39)
// grid (39 rows, 300 batches), 256 threads.
// Each block: 1 output row (39 px, padded to 40), all 128 OC.
// Thread: 4 OC x 5 px accumulators.
// ---------------------------------------------------------------------------
__global__ __launch_bounds__(256) void conv1_kernel(
    const float* __restrict__ in, const float* __restrict__ w,
    const float* __restrict__ bias)
{
    __shared__ __align__(16) float sA[16 * 516];   // [icL] -> tap*128 + oc (row stride 516)
    __shared__ float sB[16 * 84];                  // [icL][r2*42 + col], col = input col + 1

    const int oh = blockIdx.x;
    const int b  = blockIdx.y;
    const int t  = threadIdx.x;
    const int oc0 = (t >> 3) * 4;   // 32 groups of 4 OC
    const int px0 = (t & 7) * 5;    // 8 groups of 5 px

    float acc0[5] = {0,0,0,0,0};
    float acc1[5] = {0,0,0,0,0};
    float acc2[5] = {0,0,0,0,0};
    float acc3[5] = {0,0,0,0,0};

    const float4* w4 = (const float4*)w;   // one float4 = one (oc,ic): taps 0..3

    for (int chunk = 0; chunk < 16; ++chunk) {
        const int ic0 = chunk * 16;
        __syncthreads();   // protect smem reuse from previous chunk's compute
        // ---- load weights: 16 ic x 4 tap x 128 oc ----
        #pragma unroll
        for (int i = 0; i < 8; ++i) {
            int e = t + i * 256;               // 0..2047 float4s
            int oc = e >> 4, icL = e & 15;
            float4 wv = w4[oc * 256 + ic0 + icL];
            int base = icL * 516 + oc;
            sA[base        ] = wv.x;
            sA[base + 128  ] = wv.y;
            sA[base + 256  ] = wv.z;
            sA[base + 384  ] = wv.w;
        }
        // ---- zero the pad columns (0, 39, 40, 41) ----
        if (t < 128) {
            int icL = t >> 3, r2 = (t >> 2) & 1, ci = t & 3;
            int col = (ci == 0) ? 0 : 38 + ci;
            sB[icL * 84 + r2 * 42 + col] = 0.f;
        }
        // ---- load input rows oh-1, oh (16 ic x 2 rows x 38 cols) ----
        #pragma unroll
        for (int i = 0; i < 5; ++i) {
            int e = t + i * 256;
            if (e < 1216) {
                int icL = e / 76, rr = e % 76;
                int r2 = rr / 38, c = rr % 38;
                int r = oh - 1 + r2;
                float v = (r >= 0 && r < HIN)
                        ? in[((b * ICH + ic0 + icL) * HIN + r) * WIN + c] : 0.f;
                sB[icL * 84 + r2 * 42 + c + 1] = v;
            }
        }
        __syncthreads();
        // ---- compute ----
        #pragma unroll
        for (int icL = 0; icL < 16; ++icL) {
            #pragma unroll
            for (int kh = 0; kh < 2; ++kh) {
                #pragma unroll
                for (int kw = 0; kw < 2; ++kw) {
                    float4 a = *(const float4*)&sA[icL * 516 + (kh * 2 + kw) * 128 + oc0];
                    const float* bp = &sB[icL * 84 + kh * 42 + px0 + kw];
                    #pragma unroll
                    for (int p = 0; p < 5; ++p) {
                        float bv = bp[p];
                        acc0[p] += a.x * bv;
                        acc1[p] += a.y * bv;
                        acc2[p] += a.z * bv;
                        acc3[p] += a.w * bv;
                    }
                }
            }
        }
    }
    float4 bi = *(const float4*)&bias[oc0];
    #pragma unroll
    for (int p = 0; p < 5; ++p) {
        int ow = px0 + p;
        if (ow < W1D) {
            int base = ((b * OC1 + oc0) * H1 + oh) * W1D + ow;
            float v;
            v = acc0[p] + bi.x; g_x[base            ] = v > 0.f ? v : 0.f;
            v = acc1[p] + bi.y; g_x[base + NPOS1    ] = v > 0.f ? v : 0.f;
            v = acc2[p] + bi.z; g_x[base + 2*NPOS1  ] = v > 0.f ? v : 0.f;
            v = acc3[p] + bi.w; g_x[base + 3*NPOS1  ] = v > 0.f ? v : 0.f;
        }
    }
}

// ---------------------------------------------------------------------------
// K2: difference conv (Wc[a+4]-Wc[a]) + global argmax over f = a*1444 + pos.
// sigmoid is monotone => argmax of diff == argmax of softmax score.
// 1 block per batch, 256 threads, each owning 6 positions x 4 anchors.
// ---------------------------------------------------------------------------
__global__ __launch_bounds__(256) void cls_argmax_kernel(
    const float* __restrict__ Wc, const float* __restrict__ bc)
{
    __shared__ __align__(16) float wds[128 * 16];   // [ic][tap*4 + a]
    __shared__ float xs[4 * NPOS1];                 // 4 ic chunk
    __shared__ float rv[256];
    __shared__ int   rf[256];

    const int b = blockIdx.x, t = threadIdx.x;

    // weight differences: wds[ic][tap][a] = Wc[a+4] - Wc[a]
    #pragma unroll
    for (int i = 0; i < 8; ++i) {
        int e = t + i * 256;                 // 0..2047
        int ic = e >> 4, tap = (e >> 2) & 3, a = e & 3;
        wds[ic * 16 + tap * 4 + a] =
            Wc[(a + 4) * 512 + ic * 4 + tap] - Wc[a * 512 + ic * 4 + tap];
    }

    int  offs[6];
    bool valid[6];
    #pragma unroll
    for (int i = 0; i < 6; ++i) {
        int p = t + i * 256;
        valid[i] = (p < KPOS);
        int pc = valid[i] ? p : 0;
        offs[i] = (pc / 38) * 39 + (pc % 38);   // pos -> x row offset
    }

    float acc[6][4];
    #pragma unroll
    for (int i = 0; i < 6; ++i)
        #pragma unroll
        for (int a = 0; a < 4; ++a) acc[i][a] = 0.f;

    const float* xb = g_x + (size_t)b * OC1 * NPOS1;

    for (int chunk = 0; chunk < 32; ++chunk) {
        __syncthreads();
        #pragma unroll
        for (int i = 0; i < 24; ++i) {
            int e = t + i * 256;
            if (e < 4 * NPOS1) xs[e] = xb[chunk * 4 * NPOS1 + e];
        }
        __syncthreads();
        #pragma unroll
        for (int icL = 0; icL < 4; ++icL) {
            int icg = chunk * 4 + icL;
            #pragma unroll
            for (int tap = 0; tap < 4; ++tap) {
                float4 wv = *(const float4*)&wds[icg * 16 + tap * 4];
                int bidx = icL * NPOS1 + (tap >> 1) * 39 + (tap & 1);
                #pragma unroll
                for (int i = 0; i < 6; ++i) {
                    float xv = xs[bidx + offs[i]];
                    acc[i][0] += wv.x * xv;
                    acc[i][1] += wv.y * xv;
                    acc[i][2] += wv.z * xv;
                    acc[i][3] += wv.w * xv;
                }
            }
        }
    }

    float bd[4];
    #pragma unroll
    for (int a = 0; a < 4; ++a) bd[a] = bc[a + 4] - bc[a];

    float bv = -1e30f; int bf = 0x7fffffff;
    #pragma unroll
    for (int i = 0; i < 6; ++i) {
        if (valid[i]) {
            int p = t + i * 256;
            #pragma unroll
            for (int a = 0; a < 4; ++a) {
                float v = acc[i][a] + bd[a];
                int f = a * KPOS + p;
                if (v > bv || (v == bv && f < bf)) { bv = v; bf = f; }
            }
        }
    }
    rv[t] = bv; rf[t] = bf;
    __syncthreads();
    for (int s = 128; s > 0; s >>= 1) {
        if (t < s) {
            float v2 = rv[t + s]; int f2 = rf[t + s];
            if (v2 > rv[t] || (v2 == rv[t] && f2 < rf[t])) { rv[t] = v2; rf[t] = f2; }
        }
        __syncthreads();
    }
    if (t == 0) { g_bf[b] = rf[0]; g_bv[b] = rv[0]; }
}

// ---------------------------------------------------------------------------
// K3: deltas conv at the single selected position (4 channels), box assembly.
// f interpreted in proposal space: pos = f>>2, anchor = f&3.
// 1 block per batch, 128 threads (one per ic).
// ---------------------------------------------------------------------------
__global__ __launch_bounds__(128) void box_kernel(
    const float* __restrict__ Wb, const float* __restrict__ bb,
    const float* __restrict__ anchors, const float* __restrict__ im_info,
    float* __restrict__ out)
{
    __shared__ float red[4][128];
    const int b = blockIdx.x, ic = threadIdx.x;
    const int f  = g_bf[b];
    const int kp = f >> 2, ap = f & 3;
    const int hp = kp / 38, wp = kp % 38;

    const float* xb = g_x + ((size_t)b * OC1 + ic) * NPOS1 + hp * 39 + wp;
    float x0 = xb[0], x1 = xb[1], x2 = xb[39], x3 = xb[40];

    #pragma unroll
    for (int j = 0; j < 4; ++j) {
        const float* wq = Wb + (ap * 4 + j) * 512 + ic * 4;
        red[j][ic] = x0 * wq[0] + x1 * wq[1] + x2 * wq[2] + x3 * wq[3];
    }
    __syncthreads();
    if (ic < 4) {
        float s = 0.f;
        #pragma unroll 8
        for (int k = 0; k < 128; ++k) s += red[ic][k];
        s += bb[ap * 4 + ic];
        float shift = (ic & 1) ? hp * 16.f : wp * 16.f;
        float sc = im_info[0];
        float box = (anchors[ap * 4 + ic] + shift + s) * sc;
        out[b * 9 + ic]     = truncf(box / sc);
        out[b * 9 + 4 + ic] = box;
    }
    if (ic == 4) out[b * 9 + 8] = 1.f / (1.f + expf(-g_bv[b]));
}

// ---------------------------------------------------------------------------
// K4: proposal loss (single thread). Replicates reference exactly, including
// the "maximum" used for xi2/yi2.
// ---------------------------------------------------------------------------
__global__ void loss_kernel(const float* __restrict__ gt,
                            const int* __restrict__ central,
                            float* __restrict__ out, int out_size)
{
    int idx = central[0];            // FRAMES_PER_VIDEO * 0 + central_pos
    bool valid = idx < BATCH;
    int ix = idx < 0 ? 0 : (idx > BATCH - 1 ? BATCH - 1 : idx);
    float vb0 = out[ix * 9 + 4], vb1 = out[ix * 9 + 5];
    float vb2 = out[ix * 9 + 6], vb3 = out[ix * 9 + 7];
    float vs  = out[ix * 9 + 8];
    float xi1 = fmaxf(gt[0], vb0);
    float yi1 = fmaxf(gt[1], vb1);
    float xi2 = fmaxf(gt[2], vb2);
    float yi2 = fmaxf(gt[3], vb3);
    float inter = (xi2 - xi1) * (yi2 - yi1);
    float a1 = (gt[2] - gt[0]) * (gt[3] - gt[1]);
    float a2 = (vb2 - vb0) * (vb3 - vb1);
    float iou = inter / (a1 + a2 - inter);
    float lv = (iou > 0.7f) ? -logf(vs + 1e-5f) : -logf(1.f - vs + 1e-5f);
    out[out_size - 1] = valid ? lv : 0.f;
}

// ---------------------------------------------------------------------------
extern "C" void kernel_launch(void* const* d_in, const int* in_sizes, int n_in,
                              void* d_out, int out_size)
{
    const float* base_feat = (const float*)d_in[0];
    const int*   central   = (const int*)  d_in[1];
    const float* im_info   = (const float*)d_in[2];
    const float* gt_boxes  = (const float*)d_in[3];
    const float* W1        = (const float*)d_in[4];
    const float* b1        = (const float*)d_in[5];
    const float* Wc        = (const float*)d_in[6];
    const float* bc        = (const float*)d_in[7];
    const float* Wb        = (const float*)d_in[8];
    const float* bb        = (const float*)d_in[9];
    const float* anchors   = (const float*)d_in[10];
    float* out = (float*)d_out;

    conv1_kernel<<<dim3(H1, BATCH), 256>>>(base_feat, W1, b1);
    cls_argmax_kernel<<<BATCH, 256>>>(Wc, bc);
    box_kernel<<<BATCH, 128>>>(Wb, bb, anchors, im_info, out);
    loss_kernel<<<1, 1>>>(gt_boxes, central, out, out_size);
}